// round 1
// baseline (speedup 1.0000x reference)
#include <cuda_runtime.h>
#include <math.h>

// Problem dims (fixed)
#define NN_ 4096
#define DD_ 256
#define HH_ 4
#define DHH_ 256
#define QKVD_ 1024
#define OUTD_ 128

// ---------------- scratch (device globals; no cudaMalloc allowed) -------------
__device__ float g_h1[NN_ * DD_];     // elu(x@w_in + b_in + x)
__device__ float g_t1[NN_ * DD_];     // relu(h1@w_m1 + b_m1 + h1)  (pre-LN)
__device__ float g_h2[NN_ * DD_];     // LN -> attention input
__device__ float g_q[NN_ * QKVD_];
__device__ float g_k[NN_ * QKVD_];
__device__ float g_v[NN_ * QKVD_];
__device__ float g_s[(size_t)HH_ * NN_ * NN_];   // attention scores/probs (256 MiB)
__device__ float g_agg[NN_ * DD_];    // skip + mean-head aggregation
__device__ float g_t2[NN_ * DD_];     // LN(g_agg)
__device__ float g_t3[NN_ * DD_];     // relu(t2@w_m2 + b_m2 + t2)
__device__ float g_h4[NN_ * DD_];     // LN -> final

// ---------------- tiled SGEMM: C = act(alpha*A@B(^T) + bias + res (+C)) -------
// Block tile 128x128, BK=16, 256 threads, 8x8 per-thread microtile.
// All dims used here are exact multiples of the tiles (no guards).
#define BM 128
#define BN 128
#define BK 16
#define TM 8
#define TN 8

template <bool TRANSB, int ACT, bool HAS_RES, bool ACCUM>
__global__ void __launch_bounds__(256) gemm_k(
    const float* __restrict__ A, int lda, long sAb,
    const float* __restrict__ B, int ldb, long sBb,
    const float* __restrict__ bias,
    const float* __restrict__ res, int ldres,
    float* __restrict__ C, int ldc, long sCb,
    int K, float alpha)
{
    const int batch = blockIdx.z;
    A += (long)batch * sAb;
    B += (long)batch * sBb;
    C += (long)batch * sCb;

    __shared__ float As[BK][BM];
    __shared__ float Bs[BK][BN];

    const int t  = threadIdx.x;
    const int tx = t & 15;       // 0..15
    const int ty = t >> 4;       // 0..15
    const int row0 = blockIdx.y * BM;
    const int col0 = blockIdx.x * BN;

    float acc[TM][TN];
#pragma unroll
    for (int i = 0; i < TM; i++)
#pragma unroll
        for (int j = 0; j < TN; j++) acc[i][j] = 0.f;

    for (int k0 = 0; k0 < K; k0 += BK) {
        // A tile: 128 rows x 16 cols -> 512 float4, 2 per thread
#pragma unroll
        for (int i = 0; i < 2; i++) {
            int idx = t + i * 256;           // 0..511
            int r   = idx >> 2;              // 0..127
            int cb  = (idx & 3) * 4;         // 0,4,8,12
            float4 v = *reinterpret_cast<const float4*>(&A[(long)(row0 + r) * lda + k0 + cb]);
            As[cb + 0][r] = v.x; As[cb + 1][r] = v.y;
            As[cb + 2][r] = v.z; As[cb + 3][r] = v.w;
        }
        if (!TRANSB) {
            // B tile: 16 rows x 128 cols
#pragma unroll
            for (int i = 0; i < 2; i++) {
                int idx = t + i * 256;
                int r   = idx >> 5;          // k: 0..15
                int cb  = (idx & 31) * 4;    // 0..124
                float4 v = *reinterpret_cast<const float4*>(&B[(long)(k0 + r) * ldb + col0 + cb]);
                *reinterpret_cast<float4*>(&Bs[r][cb]) = v;
            }
        } else {
            // B is [N,K] row-major; Bs[k][n] = B[col0+n][k0+k]
#pragma unroll
            for (int i = 0; i < 2; i++) {
                int idx = t + i * 256;
                int r   = idx >> 2;          // n: 0..127
                int cb  = (idx & 3) * 4;     // k block
                float4 v = *reinterpret_cast<const float4*>(&B[(long)(col0 + r) * ldb + k0 + cb]);
                Bs[cb + 0][r] = v.x; Bs[cb + 1][r] = v.y;
                Bs[cb + 2][r] = v.z; Bs[cb + 3][r] = v.w;
            }
        }
        __syncthreads();

#pragma unroll
        for (int k = 0; k < BK; k++) {
            float a[TM], b[TN];
#pragma unroll
            for (int i = 0; i < TM; i++) a[i] = As[k][ty * TM + i];
#pragma unroll
            for (int j = 0; j < TN; j++) b[j] = Bs[k][tx * TN + j];
#pragma unroll
            for (int i = 0; i < TM; i++)
#pragma unroll
                for (int j = 0; j < TN; j++)
                    acc[i][j] = fmaf(a[i], b[j], acc[i][j]);
        }
        __syncthreads();
    }

    // epilogue
#pragma unroll
    for (int i = 0; i < TM; i++) {
        const int r = row0 + ty * TM + i;
#pragma unroll
        for (int j = 0; j < TN; j++) {
            const int c = col0 + tx * TN + j;
            float v = alpha * acc[i][j];
            if (bias) v += bias[c];
            if (HAS_RES) v += res[(long)r * ldres + c];
            if (ACCUM) v += C[(long)r * ldc + c];
            if (ACT == 1) v = (v > 0.f) ? v : expm1f(v);     // ELU
            if (ACT == 2) v = fmaxf(v, 0.f);                 // ReLU
            C[(long)r * ldc + c] = v;
        }
    }
}

// ---------------- block reduce helper (256 threads) ---------------------------
__device__ __forceinline__ float block_reduce_256(float v, bool do_max)
{
    __shared__ float sm[8];
#pragma unroll
    for (int o = 16; o > 0; o >>= 1) {
        float u = __shfl_xor_sync(0xffffffffu, v, o);
        v = do_max ? fmaxf(v, u) : (v + u);
    }
    const int warp = threadIdx.x >> 5;
    if ((threadIdx.x & 31) == 0) sm[warp] = v;
    __syncthreads();
    float r = sm[0];
#pragma unroll
    for (int i = 1; i < 8; i++) r = do_max ? fmaxf(r, sm[i]) : (r + sm[i]);
    __syncthreads();   // protect smem reuse across successive calls
    return r;
}

// ---------------- softmax over rows of length 4096 (in place) -----------------
// One block per row; each thread keeps its 16 elements in registers.
__global__ void __launch_bounds__(256) softmax_k(float* __restrict__ S)
{
    const long row = blockIdx.x;
    float* p = S + row * (long)NN_;
    const int t = threadIdx.x;

    float v[16];
    float m = -1e30f;
#pragma unroll
    for (int i = 0; i < 16; i++) { v[i] = p[i * 256 + t]; m = fmaxf(m, v[i]); }
    m = block_reduce_256(m, true);

    float s = 0.f;
#pragma unroll
    for (int i = 0; i < 16; i++) { v[i] = __expf(v[i] - m); s += v[i]; }
    s = block_reduce_256(s, false);

    const float inv = 1.f / s;
#pragma unroll
    for (int i = 0; i < 16; i++) p[i * 256 + t] = v[i] * inv;
}

// ---------------- LayerNorm over rows of length 256 ---------------------------
__global__ void __launch_bounds__(256) ln_k(
    const float* __restrict__ X, const float* __restrict__ g,
    const float* __restrict__ b, float* __restrict__ Y)
{
    const int row = blockIdx.x;
    const int t = threadIdx.x;
    const float x = X[row * DD_ + t];
    const float mean = block_reduce_256(x, false) * (1.f / 256.f);
    const float d = x - mean;
    const float var = block_reduce_256(d * d, false) * (1.f / 256.f);
    Y[row * DD_ + t] = d * rsqrtf(var + 1e-5f) * g[t] + b[t];
}

// ---------------- launch -------------------------------------------------------
extern "C" void kernel_launch(void* const* d_in, const int* in_sizes, int n_in,
                              void* d_out, int out_size)
{
    const float* x      = (const float*)d_in[0];
    const float* w_in   = (const float*)d_in[1];
    const float* b_in   = (const float*)d_in[2];
    const float* w_m1   = (const float*)d_in[3];
    const float* b_m1   = (const float*)d_in[4];
    const float* g_m1   = (const float*)d_in[5];
    const float* be_m1  = (const float*)d_in[6];
    const float* wq     = (const float*)d_in[7];
    const float* bq     = (const float*)d_in[8];
    const float* wk     = (const float*)d_in[9];
    const float* bk     = (const float*)d_in[10];
    const float* wv     = (const float*)d_in[11];
    const float* bv     = (const float*)d_in[12];
    const float* wskip  = (const float*)d_in[13];
    const float* bskip  = (const float*)d_in[14];
    const float* g_n1   = (const float*)d_in[15];
    const float* be_n1  = (const float*)d_in[16];
    const float* w_m2   = (const float*)d_in[17];
    const float* b_m2   = (const float*)d_in[18];
    const float* g_m2   = (const float*)d_in[19];
    const float* be_m2  = (const float*)d_in[20];
    const float* w_mean = (const float*)d_in[21];
    const float* b_mean = (const float*)d_in[22];
    float* out = (float*)d_out;

    float *h1, *t1, *h2, *q, *k, *v, *s, *agg, *t2, *t3, *h4;
    cudaGetSymbolAddress((void**)&h1,  g_h1);
    cudaGetSymbolAddress((void**)&t1,  g_t1);
    cudaGetSymbolAddress((void**)&h2,  g_h2);
    cudaGetSymbolAddress((void**)&q,   g_q);
    cudaGetSymbolAddress((void**)&k,   g_k);
    cudaGetSymbolAddress((void**)&v,   g_v);
    cudaGetSymbolAddress((void**)&s,   g_s);
    cudaGetSymbolAddress((void**)&agg, g_agg);
    cudaGetSymbolAddress((void**)&t2,  g_t2);
    cudaGetSymbolAddress((void**)&t3,  g_t3);
    cudaGetSymbolAddress((void**)&h4,  g_h4);

    const dim3 blk(256);
    const dim3 gSq(DD_ / BN, NN_ / BM);      // (2, 32)  N=256
    const dim3 gQkv(QKVD_ / BN, NN_ / BM);   // (8, 32)  N=1024
    const dim3 gOut(OUTD_ / BN, NN_ / BM);   // (1, 32)  N=128
    const dim3 gScore(NN_ / BN, NN_ / BM, HH_); // (32,32,4)

    // 1) h1 = elu(x @ w_in + b_in + x)
    gemm_k<false, 1, true, false><<<gSq, blk>>>(x, DD_, 0, w_in, DD_, 0,
        b_in, x, DD_, h1, DD_, 0, DD_, 1.f);

    // 2) t1 = relu(h1 @ w_m1 + b_m1 + h1);  h2 = LN(t1; g_m1, be_m1)
    gemm_k<false, 2, true, false><<<gSq, blk>>>(h1, DD_, 0, w_m1, DD_, 0,
        b_m1, h1, DD_, t1, DD_, 0, DD_, 1.f);
    ln_k<<<NN_, blk>>>(t1, g_m1, be_m1, h2);

    // 3) q/k/v = h2 @ w{q,k,v} + b{q,k,v}
    gemm_k<false, 0, false, false><<<gQkv, blk>>>(h2, DD_, 0, wq, QKVD_, 0,
        bq, nullptr, 0, q, QKVD_, 0, DD_, 1.f);
    gemm_k<false, 0, false, false><<<gQkv, blk>>>(h2, DD_, 0, wk, QKVD_, 0,
        bk, nullptr, 0, k, QKVD_, 0, DD_, 1.f);
    gemm_k<false, 0, false, false><<<gQkv, blk>>>(h2, DD_, 0, wv, QKVD_, 0,
        bv, nullptr, 0, v, QKVD_, 0, DD_, 1.f);

    // 4) scores: s[h] = (1/16) * Q_h @ K_h^T   (batched over heads via grid.z)
    gemm_k<true, 0, false, false><<<gScore, blk>>>(q, QKVD_, DHH_, k, QKVD_, DHH_,
        nullptr, nullptr, 0, s, NN_, (long)NN_ * NN_, DHH_, 1.f / 16.f);

    // 5) softmax over source nodes (rows of length 4096)
    softmax_k<<<HH_ * NN_, blk>>>(s);

    // 6) agg = h2 @ wskip + bskip
    gemm_k<false, 0, false, false><<<gSq, blk>>>(h2, DD_, 0, wskip, DD_, 0,
        bskip, nullptr, 0, agg, DD_, 0, DD_, 1.f);

    // 7) agg += 0.25 * P_h @ V_h   (sequential per head: accumulation)
    for (int h = 0; h < HH_; h++) {
        gemm_k<false, 0, false, true><<<gSq, blk>>>(
            s + (long)h * NN_ * NN_, NN_, 0,
            v + (long)h * DHH_, QKVD_, 0,
            nullptr, nullptr, 0, agg, DD_, 0, NN_, 0.25f);
    }

    // 8) t2 = LN(agg; g_n1, be_n1)
    ln_k<<<NN_, blk>>>(agg, g_n1, be_n1, t2);

    // 9) t3 = relu(t2 @ w_m2 + b_m2 + t2);  h4 = LN(t3; g_m2, be_m2)
    gemm_k<false, 2, true, false><<<gSq, blk>>>(t2, DD_, 0, w_m2, DD_, 0,
        b_m2, t2, DD_, t3, DD_, 0, DD_, 1.f);
    ln_k<<<NN_, blk>>>(t3, g_m2, be_m2, h4);

    // 10) out = h4 @ w_mean + b_mean
    gemm_k<false, 0, false, false><<<gOut, blk>>>(h4, DD_, 0, w_mean, OUTD_, 0,
        b_mean, nullptr, 0, out, OUTD_, 0, DD_, 1.f);
}

// round 2
// speedup vs baseline: 2.0726x; 2.0726x over previous
#include <cuda_runtime.h>
#include <math.h>
#include <stdint.h>

// Problem dims (fixed)
#define NN_ 4096
#define DD_ 256
#define HH_ 4
#define DHH_ 256
#define QKVD_ 1024
#define OUTD_ 128

// ---------------- scratch (device globals; no cudaMalloc allowed) -------------
__device__ float g_h1[NN_ * DD_];
__device__ float g_t1[NN_ * DD_];
__device__ float g_h2[NN_ * DD_];
__device__ float g_q[NN_ * QKVD_];
__device__ float g_k[NN_ * QKVD_];
__device__ float g_v[NN_ * QKVD_];
__device__ float g_s[(size_t)HH_ * NN_ * NN_];   // attention scores/probs (256 MiB)
__device__ float g_agg[NN_ * DD_];
__device__ float g_t2[NN_ * DD_];
__device__ float g_t3[NN_ * DD_];
__device__ float g_h4[NN_ * DD_];

// ---------------- TF32 tensor-core GEMM ---------------------------------------
// C = act(alpha*A@B(^T) + bias + res (+C)), A [M,K] row-major.
// TRANSB=false: B [K,N] row-major. TRANSB=true: B [N,K] row-major (B^T used).
// Block tile 128x128, BK=32. 256 threads = 8 warps (2 M x 4 N), warp tile 64x32,
// computed as 4x4 atoms of mma.sync.m16n8k8.tf32.
#define BM 128
#define BN 128
#define BK 32
#define PA 133   // As row pad (k-major [k][m]) -> conflict-free frag loads/stores
#define PB 132   // Bs row pad ([k][n]), multiple of 4 for uint4 stores

__device__ __forceinline__ uint32_t f2tf32(float f) {
    uint32_t u;
    asm("cvt.rna.tf32.f32 %0, %1;" : "=r"(u) : "f"(f));
    return u;
}

__device__ __forceinline__ void mma_tf32(float* d, const uint32_t* a, const uint32_t* b) {
    asm volatile(
        "mma.sync.aligned.m16n8k8.row.col.f32.tf32.tf32.f32 "
        "{%0,%1,%2,%3}, {%4,%5,%6,%7}, {%8,%9}, {%0,%1,%2,%3};\n"
        : "+f"(d[0]), "+f"(d[1]), "+f"(d[2]), "+f"(d[3])
        : "r"(a[0]), "r"(a[1]), "r"(a[2]), "r"(a[3]), "r"(b[0]), "r"(b[1]));
}

template <bool TRANSB, int ACT, bool HAS_RES, bool ACCUM>
__global__ void __launch_bounds__(256) gemm_tc(
    const float* __restrict__ A, int lda, long sAb,
    const float* __restrict__ B, int ldb, long sBb,
    const float* __restrict__ bias,
    const float* __restrict__ res, int ldres,
    float* __restrict__ C, int ldc, long sCb,
    int K, float alpha)
{
    const int batch = blockIdx.z;
    A += (long)batch * sAb;
    B += (long)batch * sBb;
    C += (long)batch * sCb;

    __shared__ uint32_t As[BK * PA];   // As[k][m]
    __shared__ uint32_t Bs[BK * PB];   // Bs[k][n]

    const int t    = threadIdx.x;
    const int warp = t >> 5;
    const int lane = t & 31;
    const int g    = lane >> 2;     // group id 0..7
    const int tig  = lane & 3;      // thread-in-group 0..3
    const int m0   = (warp >> 2) * 64;   // warp M origin in tile
    const int n0   = (warp & 3) * 32;    // warp N origin in tile
    const int row0 = blockIdx.y * BM;
    const int col0 = blockIdx.x * BN;

    float d[4][4][4];
#pragma unroll
    for (int am = 0; am < 4; am++)
#pragma unroll
        for (int an = 0; an < 4; an++)
#pragma unroll
            for (int i = 0; i < 4; i++) d[am][an][i] = 0.f;

    for (int k0 = 0; k0 < K; k0 += BK) {
        // ---- stage A: 128 rows x 32 cols, 4 float4/thread, store k-major ----
#pragma unroll
        for (int i = 0; i < 4; i++) {
            int idx = t + i * 256;          // 0..1023
            int r   = idx >> 3;             // 0..127 (m)
            int cb  = (idx & 7) * 4;        // 0..28  (k)
            float4 v = *reinterpret_cast<const float4*>(&A[(long)(row0 + r) * lda + k0 + cb]);
            As[(cb + 0) * PA + r] = f2tf32(v.x);
            As[(cb + 1) * PA + r] = f2tf32(v.y);
            As[(cb + 2) * PA + r] = f2tf32(v.z);
            As[(cb + 3) * PA + r] = f2tf32(v.w);
        }
        if (TRANSB) {
            // B [N,K]: 128 rows (n) x 32 cols (k), store transposed into Bs[k][n]
#pragma unroll
            for (int i = 0; i < 4; i++) {
                int idx = t + i * 256;
                int r   = idx >> 3;          // n
                int cb  = (idx & 7) * 4;     // k
                float4 v = *reinterpret_cast<const float4*>(&B[(long)(col0 + r) * ldb + k0 + cb]);
                Bs[(cb + 0) * PB + r] = f2tf32(v.x);
                Bs[(cb + 1) * PB + r] = f2tf32(v.y);
                Bs[(cb + 2) * PB + r] = f2tf32(v.z);
                Bs[(cb + 3) * PB + r] = f2tf32(v.w);
            }
        } else {
            // B [K,N]: 32 rows (k) x 128 cols (n), direct row-major store
#pragma unroll
            for (int i = 0; i < 4; i++) {
                int idx = t + i * 256;
                int r   = idx >> 5;          // k 0..31
                int cb  = (idx & 31) * 4;    // n 0..124
                float4 v = *reinterpret_cast<const float4*>(&B[(long)(k0 + r) * ldb + col0 + cb]);
                uint4 u;
                u.x = f2tf32(v.x); u.y = f2tf32(v.y);
                u.z = f2tf32(v.z); u.w = f2tf32(v.w);
                *reinterpret_cast<uint4*>(&Bs[r * PB + cb]) = u;
            }
        }
        __syncthreads();

#pragma unroll
        for (int ks = 0; ks < BK / 8; ks++) {
            const int kk = ks * 8;
            uint32_t a[4][4], b[4][2];
#pragma unroll
            for (int am = 0; am < 4; am++) {
                const int mr = m0 + am * 16 + g;
                a[am][0] = As[(kk + tig) * PA + mr];
                a[am][1] = As[(kk + tig) * PA + mr + 8];
                a[am][2] = As[(kk + tig + 4) * PA + mr];
                a[am][3] = As[(kk + tig + 4) * PA + mr + 8];
            }
#pragma unroll
            for (int an = 0; an < 4; an++) {
                const int nc = n0 + an * 8 + g;
                b[an][0] = Bs[(kk + tig) * PB + nc];
                b[an][1] = Bs[(kk + tig + 4) * PB + nc];
            }
#pragma unroll
            for (int am = 0; am < 4; am++)
#pragma unroll
                for (int an = 0; an < 4; an++)
                    mma_tf32(d[am][an], a[am], b[an]);
        }
        __syncthreads();
    }

    // ---- epilogue: each atom owns (r,c0..c0+1) and (r+8,c0..c0+1) ----
#pragma unroll
    for (int am = 0; am < 4; am++) {
#pragma unroll
        for (int an = 0; an < 4; an++) {
            const int c0 = col0 + n0 + an * 8 + tig * 2;
#pragma unroll
            for (int half = 0; half < 2; half++) {
                const int r = row0 + m0 + am * 16 + g + half * 8;
#pragma unroll
                for (int j = 0; j < 2; j++) {
                    const int c = c0 + j;
                    float v = alpha * d[am][an][half * 2 + j];
                    if (bias) v += bias[c];
                    if (HAS_RES) v += res[(long)r * ldres + c];
                    if (ACCUM) v += C[(long)r * ldc + c];
                    if (ACT == 1) v = (v > 0.f) ? v : expm1f(v);   // ELU
                    if (ACT == 2) v = fmaxf(v, 0.f);               // ReLU
                    C[(long)r * ldc + c] = v;
                }
            }
        }
    }
}

// ---------------- block reduce helper (256 threads) ---------------------------
__device__ __forceinline__ float block_reduce_256(float v, bool do_max)
{
    __shared__ float sm[8];
#pragma unroll
    for (int o = 16; o > 0; o >>= 1) {
        float u = __shfl_xor_sync(0xffffffffu, v, o);
        v = do_max ? fmaxf(v, u) : (v + u);
    }
    const int warp = threadIdx.x >> 5;
    if ((threadIdx.x & 31) == 0) sm[warp] = v;
    __syncthreads();
    float r = sm[0];
#pragma unroll
    for (int i = 1; i < 8; i++) r = do_max ? fmaxf(r, sm[i]) : (r + sm[i]);
    __syncthreads();
    return r;
}

// ---------------- softmax over rows of length 4096 (in place) -----------------
__global__ void __launch_bounds__(256) softmax_k(float* __restrict__ S)
{
    const long row = blockIdx.x;
    float* p = S + row * (long)NN_;
    const int t = threadIdx.x;

    float v[16];
    float m = -1e30f;
#pragma unroll
    for (int i = 0; i < 16; i++) { v[i] = p[i * 256 + t]; m = fmaxf(m, v[i]); }
    m = block_reduce_256(m, true);

    float s = 0.f;
#pragma unroll
    for (int i = 0; i < 16; i++) { v[i] = __expf(v[i] - m); s += v[i]; }
    s = block_reduce_256(s, false);

    const float inv = 1.f / s;
#pragma unroll
    for (int i = 0; i < 16; i++) p[i * 256 + t] = v[i] * inv;
}

// ---------------- LayerNorm over rows of length 256 ---------------------------
__global__ void __launch_bounds__(256) ln_k(
    const float* __restrict__ X, const float* __restrict__ g,
    const float* __restrict__ b, float* __restrict__ Y)
{
    const int row = blockIdx.x;
    const int t = threadIdx.x;
    const float x = X[row * DD_ + t];
    const float mean = block_reduce_256(x, false) * (1.f / 256.f);
    const float d = x - mean;
    const float var = block_reduce_256(d * d, false) * (1.f / 256.f);
    Y[row * DD_ + t] = d * rsqrtf(var + 1e-5f) * g[t] + b[t];
}

// ---------------- launch -------------------------------------------------------
extern "C" void kernel_launch(void* const* d_in, const int* in_sizes, int n_in,
                              void* d_out, int out_size)
{
    const float* x      = (const float*)d_in[0];
    const float* w_in   = (const float*)d_in[1];
    const float* b_in   = (const float*)d_in[2];
    const float* w_m1   = (const float*)d_in[3];
    const float* b_m1   = (const float*)d_in[4];
    const float* g_m1   = (const float*)d_in[5];
    const float* be_m1  = (const float*)d_in[6];
    const float* wq     = (const float*)d_in[7];
    const float* bq     = (const float*)d_in[8];
    const float* wk     = (const float*)d_in[9];
    const float* bk     = (const float*)d_in[10];
    const float* wv     = (const float*)d_in[11];
    const float* bv     = (const float*)d_in[12];
    const float* wskip  = (const float*)d_in[13];
    const float* bskip  = (const float*)d_in[14];
    const float* g_n1   = (const float*)d_in[15];
    const float* be_n1  = (const float*)d_in[16];
    const float* w_m2   = (const float*)d_in[17];
    const float* b_m2   = (const float*)d_in[18];
    const float* g_m2   = (const float*)d_in[19];
    const float* be_m2  = (const float*)d_in[20];
    const float* w_mean = (const float*)d_in[21];
    const float* b_mean = (const float*)d_in[22];
    float* out = (float*)d_out;

    float *h1, *t1, *h2, *q, *k, *v, *s, *agg, *t2, *t3, *h4;
    cudaGetSymbolAddress((void**)&h1,  g_h1);
    cudaGetSymbolAddress((void**)&t1,  g_t1);
    cudaGetSymbolAddress((void**)&h2,  g_h2);
    cudaGetSymbolAddress((void**)&q,   g_q);
    cudaGetSymbolAddress((void**)&k,   g_k);
    cudaGetSymbolAddress((void**)&v,   g_v);
    cudaGetSymbolAddress((void**)&s,   g_s);
    cudaGetSymbolAddress((void**)&agg, g_agg);
    cudaGetSymbolAddress((void**)&t2,  g_t2);
    cudaGetSymbolAddress((void**)&t3,  g_t3);
    cudaGetSymbolAddress((void**)&h4,  g_h4);

    const dim3 blk(256);
    const dim3 gSq(DD_ / BN, NN_ / BM);         // (2, 32)
    const dim3 gQkv(QKVD_ / BN, NN_ / BM);      // (8, 32)
    const dim3 gOut(OUTD_ / BN, NN_ / BM);      // (1, 32)
    const dim3 gScore(NN_ / BN, NN_ / BM, HH_); // (32, 32, 4)

    // 1) h1 = elu(x @ w_in + b_in + x)
    gemm_tc<false, 1, true, false><<<gSq, blk>>>(x, DD_, 0, w_in, DD_, 0,
        b_in, x, DD_, h1, DD_, 0, DD_, 1.f);

    // 2) t1 = relu(h1 @ w_m1 + b_m1 + h1);  h2 = LN(t1)
    gemm_tc<false, 2, true, false><<<gSq, blk>>>(h1, DD_, 0, w_m1, DD_, 0,
        b_m1, h1, DD_, t1, DD_, 0, DD_, 1.f);
    ln_k<<<NN_, blk>>>(t1, g_m1, be_m1, h2);

    // 3) q/k/v projections
    gemm_tc<false, 0, false, false><<<gQkv, blk>>>(h2, DD_, 0, wq, QKVD_, 0,
        bq, nullptr, 0, q, QKVD_, 0, DD_, 1.f);
    gemm_tc<false, 0, false, false><<<gQkv, blk>>>(h2, DD_, 0, wk, QKVD_, 0,
        bk, nullptr, 0, k, QKVD_, 0, DD_, 1.f);
    gemm_tc<false, 0, false, false><<<gQkv, blk>>>(h2, DD_, 0, wv, QKVD_, 0,
        bv, nullptr, 0, v, QKVD_, 0, DD_, 1.f);

    // 4) scores: s[h] = (1/16) * Q_h @ K_h^T
    gemm_tc<true, 0, false, false><<<gScore, blk>>>(q, QKVD_, DHH_, k, QKVD_, DHH_,
        nullptr, nullptr, 0, s, NN_, (long)NN_ * NN_, DHH_, 1.f / 16.f);

    // 5) softmax over source nodes
    softmax_k<<<HH_ * NN_, blk>>>(s);

    // 6) agg = h2 @ wskip + bskip
    gemm_tc<false, 0, false, false><<<gSq, blk>>>(h2, DD_, 0, wskip, DD_, 0,
        bskip, nullptr, 0, agg, DD_, 0, DD_, 1.f);

    // 7) agg += 0.25 * P_h @ V_h  (sequential per head)
    for (int h = 0; h < HH_; h++) {
        gemm_tc<false, 0, false, true><<<gSq, blk>>>(
            s + (long)h * NN_ * NN_, NN_, 0,
            v + (long)h * DHH_, QKVD_, 0,
            nullptr, nullptr, 0, agg, DD_, 0, NN_, 0.25f);
    }

    // 8) t2 = LN(agg)
    ln_k<<<NN_, blk>>>(agg, g_n1, be_n1, t2);

    // 9) t3 = relu(t2 @ w_m2 + b_m2 + t2);  h4 = LN(t3)
    gemm_tc<false, 2, true, false><<<gSq, blk>>>(t2, DD_, 0, w_m2, DD_, 0,
        b_m2, t2, DD_, t3, DD_, 0, DD_, 1.f);
    ln_k<<<NN_, blk>>>(t3, g_m2, be_m2, h4);

    // 10) out = h4 @ w_mean + b_mean
    gemm_tc<false, 0, false, false><<<gOut, blk>>>(h4, DD_, 0, w_mean, OUTD_, 0,
        b_mean, nullptr, 0, out, OUTD_, 0, DD_, 1.f);
}

// round 5
// speedup vs baseline: 3.9297x; 1.8960x over previous
#include <cuda_runtime.h>
#include <math.h>
#include <stdint.h>

// Problem dims (fixed)
#define NN_ 4096
#define DD_ 256
#define HH_ 4
#define DHH_ 256
#define QKVD_ 1024
#define OUTD_ 128

// ---------------- scratch (device globals) ------------------------------------
__device__ float g_h1[NN_ * DD_];
__device__ float g_t1[NN_ * DD_];
__device__ float g_h2[NN_ * DD_];
__device__ float g_q[NN_ * QKVD_];     // later reused as 4 per-head PV outputs
__device__ float g_k[NN_ * QKVD_];
__device__ float g_v[NN_ * QKVD_];
__device__ float g_s[(size_t)HH_ * NN_ * NN_];
__device__ float g_agg[NN_ * DD_];
__device__ float g_t2[NN_ * DD_];
__device__ float g_t3[NN_ * DD_];
__device__ float g_h4[NN_ * DD_];

__device__ __forceinline__ uint32_t f2tf32(float f) {
    uint32_t u;
    asm("cvt.rna.tf32.f32 %0, %1;" : "=r"(u) : "f"(f));
    return u;
}

__device__ __forceinline__ void mma_tf32(float* d, const uint32_t* a, const uint32_t* b) {
    asm volatile(
        "mma.sync.aligned.m16n8k8.row.col.f32.tf32.tf32.f32 "
        "{%0,%1,%2,%3}, {%4,%5,%6,%7}, {%8,%9}, {%0,%1,%2,%3};\n"
        : "+f"(d[0]), "+f"(d[1]), "+f"(d[2]), "+f"(d[3])
        : "r"(a[0]), "r"(a[1]), "r"(a[2]), "r"(a[3]), "r"(b[0]), "r"(b[1]));
}

// ---------------- TF32 tensor-core GEMM, register-double-buffered --------------
// C = act(alpha*A@B(^T) + bias + res), A [M,K] row-major.
// 128 threads = 4 warps (2x2), warp tile WM x WN of m16n8k8 atoms, BK=16.
template <int BM, int BN, int WM, int WN, bool TRANSB, int ACT, bool HAS_RES>
__global__ void __launch_bounds__(128, 2) gemm_tc(
    const float* __restrict__ A, int lda, long sAb,
    const float* __restrict__ B, int ldb, long sBb,
    const float* __restrict__ bias,
    const float* __restrict__ res, int ldres,
    float* __restrict__ C, int ldc, long sCb,
    int K, float alpha)
{
    constexpr int BK = 16;
    constexpr int AM = WM / 16;
    constexpr int AN = WN / 8;
    constexpr int PA = BM + 5;
    constexpr int PB = TRANSB ? (BN + 5) : (BN + 8);
    constexpr int NA = BM * BK / (128 * 4);   // float4 per thread (A tile)
    constexpr int NB = BK * BN / (128 * 4);   // float4 per thread (B tile)

    const int batch = blockIdx.z;
    A += (long)batch * sAb;
    B += (long)batch * sBb;
    C += (long)batch * sCb;

    __shared__ __align__(16) uint32_t As[BK * PA];
    __shared__ __align__(16) uint32_t Bs[BK * PB];

    const int t    = threadIdx.x;
    const int warp = t >> 5;
    const int lane = t & 31;
    const int g    = lane >> 2;
    const int tig  = lane & 3;
    const int wm0  = (warp >> 1) * WM;
    const int wn0  = (warp & 1) * WN;
    const int row0 = blockIdx.y * BM;
    const int col0 = blockIdx.x * BN;

    float d[AM][AN][4];
#pragma unroll
    for (int am = 0; am < AM; am++)
#pragma unroll
        for (int an = 0; an < AN; an++)
#pragma unroll
            for (int i = 0; i < 4; i++) d[am][an][i] = 0.f;

    float4 ar[NA], br[NB];

    // ---- loaders (gmem -> regs) ----
    auto loadA = [&](int k0) {
#pragma unroll
        for (int i = 0; i < NA; i++) {
            int idx = t + i * 128;
            int r   = idx >> 2;            // 0..BM-1
            int cb  = (idx & 3) * 4;       // 0..12
            ar[i] = *reinterpret_cast<const float4*>(&A[(long)(row0 + r) * lda + k0 + cb]);
        }
    };
    auto loadB = [&](int k0) {
        if (TRANSB) {
#pragma unroll
            for (int i = 0; i < NB; i++) {
                int idx = t + i * 128;
                int n   = (idx & 7) + (idx >> 5) * 8;   // 0..BN-1
                int cb  = ((idx >> 3) & 3) * 4;         // 0..12
                br[i] = *reinterpret_cast<const float4*>(&B[(long)(col0 + n) * ldb + k0 + cb]);
            }
        } else {
#pragma unroll
            for (int i = 0; i < NB; i++) {
                int idx = t + i * 128;
                int r   = idx / (BN / 4);               // k
                int cb  = (idx % (BN / 4)) * 4;         // n
                br[i] = *reinterpret_cast<const float4*>(&B[(long)(k0 + r) * ldb + col0 + cb]);
            }
        }
    };
    // ---- stores (regs -> smem, tf32 round) ----
    auto storeA = [&]() {
#pragma unroll
        for (int i = 0; i < NA; i++) {
            int idx = t + i * 128;
            int r   = idx >> 2;
            int cb  = (idx & 3) * 4;
            As[(cb + 0) * PA + r] = f2tf32(ar[i].x);
            As[(cb + 1) * PA + r] = f2tf32(ar[i].y);
            As[(cb + 2) * PA + r] = f2tf32(ar[i].z);
            As[(cb + 3) * PA + r] = f2tf32(ar[i].w);
        }
    };
    auto storeB = [&]() {
        if (TRANSB) {
#pragma unroll
            for (int i = 0; i < NB; i++) {
                int idx = t + i * 128;
                int n   = (idx & 7) + (idx >> 5) * 8;
                int cb  = ((idx >> 3) & 3) * 4;
                Bs[(cb + 0) * PB + n] = f2tf32(br[i].x);
                Bs[(cb + 1) * PB + n] = f2tf32(br[i].y);
                Bs[(cb + 2) * PB + n] = f2tf32(br[i].z);
                Bs[(cb + 3) * PB + n] = f2tf32(br[i].w);
            }
        } else {
#pragma unroll
            for (int i = 0; i < NB; i++) {
                int idx = t + i * 128;
                int r   = idx / (BN / 4);
                int cb  = (idx % (BN / 4)) * 4;
                uint4 u;
                u.x = f2tf32(br[i].x); u.y = f2tf32(br[i].y);
                u.z = f2tf32(br[i].z); u.w = f2tf32(br[i].w);
                *reinterpret_cast<uint4*>(&Bs[r * PB + cb]) = u;
            }
        }
    };

    // ---- prologue ----
    loadA(0); loadB(0);
    storeA(); storeB();
    __syncthreads();

    for (int k0 = 0; k0 < K; k0 += BK) {
        const bool nxt = (k0 + BK) < K;
        if (nxt) { loadA(k0 + BK); loadB(k0 + BK); }

#pragma unroll
        for (int ks = 0; ks < 2; ks++) {
            const int kk = ks * 8;
            uint32_t a[AM][4], b[AN][2];
#pragma unroll
            for (int am = 0; am < AM; am++) {
                const int mr = wm0 + am * 16 + g;
                a[am][0] = As[(kk + tig) * PA + mr];
                a[am][1] = As[(kk + tig) * PA + mr + 8];
                a[am][2] = As[(kk + tig + 4) * PA + mr];
                a[am][3] = As[(kk + tig + 4) * PA + mr + 8];
            }
#pragma unroll
            for (int an = 0; an < AN; an++) {
                const int nc = wn0 + an * 8 + g;
                b[an][0] = Bs[(kk + tig) * PB + nc];
                b[an][1] = Bs[(kk + tig + 4) * PB + nc];
            }
#pragma unroll
            for (int am = 0; am < AM; am++)
#pragma unroll
                for (int an = 0; an < AN; an++)
                    mma_tf32(d[am][an], a[am], b[an]);
        }

        if (nxt) {
            __syncthreads();
            storeA(); storeB();
            __syncthreads();
        }
    }

    // ---- epilogue ----
#pragma unroll
    for (int am = 0; am < AM; am++) {
#pragma unroll
        for (int an = 0; an < AN; an++) {
            const int c0 = col0 + wn0 + an * 8 + tig * 2;
#pragma unroll
            for (int half = 0; half < 2; half++) {
                const int r = row0 + wm0 + am * 16 + g + half * 8;
#pragma unroll
                for (int j = 0; j < 2; j++) {
                    const int c = c0 + j;
                    float v = alpha * d[am][an][half * 2 + j];
                    if (bias) v += bias[c];
                    if (HAS_RES) v += res[(long)r * ldres + c];
                    if (ACT == 1) v = (v > 0.f) ? v : expm1f(v);   // ELU
                    if (ACT == 2) v = fmaxf(v, 0.f);               // ReLU
                    C[(long)r * ldc + c] = v;
                }
            }
        }
    }
}

// ---------------- block reduce (256 threads) -----------------------------------
__device__ __forceinline__ float block_reduce_256(float v, bool do_max)
{
    __shared__ float sm[8];
#pragma unroll
    for (int o = 16; o > 0; o >>= 1) {
        float u = __shfl_xor_sync(0xffffffffu, v, o);
        v = do_max ? fmaxf(v, u) : (v + u);
    }
    const int warp = threadIdx.x >> 5;
    if ((threadIdx.x & 31) == 0) sm[warp] = v;
    __syncthreads();
    float r = sm[0];
#pragma unroll
    for (int i = 1; i < 8; i++) r = do_max ? fmaxf(r, sm[i]) : (r + sm[i]);
    __syncthreads();
    return r;
}

// ---------------- softmax over rows of 4096 (in place) -------------------------
__global__ void __launch_bounds__(256) softmax_k(float* __restrict__ S)
{
    const long row = blockIdx.x;
    float* p = S + row * (long)NN_;
    const int t = threadIdx.x;

    float v[16];
    float m = -1e30f;
#pragma unroll
    for (int i = 0; i < 16; i++) { v[i] = p[i * 256 + t]; m = fmaxf(m, v[i]); }
    m = block_reduce_256(m, true);

    float s = 0.f;
#pragma unroll
    for (int i = 0; i < 16; i++) { v[i] = __expf(v[i] - m); s += v[i]; }
    s = block_reduce_256(s, false);

    const float inv = 1.f / s;
#pragma unroll
    for (int i = 0; i < 16; i++) p[i * 256 + t] = v[i] * inv;
}

// ---------------- LayerNorm over rows of 256 -----------------------------------
__global__ void __launch_bounds__(256) ln_k(
    const float* __restrict__ X, const float* __restrict__ g,
    const float* __restrict__ b, float* __restrict__ Y)
{
    const int row = blockIdx.x;
    const int t = threadIdx.x;
    const float x = X[row * DD_ + t];
    const float mean = block_reduce_256(x, false) * (1.f / 256.f);
    const float d = x - mean;
    const float var = block_reduce_256(d * d, false) * (1.f / 256.f);
    Y[row * DD_ + t] = d * rsqrtf(var + 1e-5f) * g[t] + b[t];
}

// ---- LN of (skip + sum of 4 per-head PV outputs), heads pre-scaled by 0.25 ----
__global__ void __launch_bounds__(256) ln_agg_k(
    const float* __restrict__ skip, const float* __restrict__ ph,
    const float* __restrict__ g, const float* __restrict__ b,
    float* __restrict__ Y)
{
    const int row = blockIdx.x;
    const int t = threadIdx.x;
    const long i = (long)row * DD_ + t;
    const long S = (long)NN_ * DD_;
    const float x = skip[i] + ph[i] + ph[i + S] + ph[i + 2 * S] + ph[i + 3 * S];
    const float mean = block_reduce_256(x, false) * (1.f / 256.f);
    const float d = x - mean;
    const float var = block_reduce_256(d * d, false) * (1.f / 256.f);
    Y[row * DD_ + t] = d * rsqrtf(var + 1e-5f) * g[t] + b[t];
}

// ---------------- launch --------------------------------------------------------
extern "C" void kernel_launch(void* const* d_in, const int* in_sizes, int n_in,
                              void* d_out, int out_size)
{
    const float* x      = (const float*)d_in[0];
    const float* w_in   = (const float*)d_in[1];
    const float* b_in   = (const float*)d_in[2];
    const float* w_m1   = (const float*)d_in[3];
    const float* b_m1   = (const float*)d_in[4];
    const float* g_m1   = (const float*)d_in[5];
    const float* be_m1  = (const float*)d_in[6];
    const float* wq     = (const float*)d_in[7];
    const float* bq     = (const float*)d_in[8];
    const float* wk     = (const float*)d_in[9];
    const float* bk     = (const float*)d_in[10];
    const float* wv     = (const float*)d_in[11];
    const float* bv     = (const float*)d_in[12];
    const float* wskip  = (const float*)d_in[13];
    const float* bskip  = (const float*)d_in[14];
    const float* g_n1   = (const float*)d_in[15];
    const float* be_n1  = (const float*)d_in[16];
    const float* w_m2   = (const float*)d_in[17];
    const float* b_m2   = (const float*)d_in[18];
    const float* g_m2   = (const float*)d_in[19];
    const float* be_m2  = (const float*)d_in[20];
    const float* w_mean = (const float*)d_in[21];
    const float* b_mean = (const float*)d_in[22];
    float* out = (float*)d_out;

    float *h1, *t1, *h2, *q, *k, *v, *s, *agg, *t2, *t3, *h4;
    cudaGetSymbolAddress((void**)&h1,  g_h1);
    cudaGetSymbolAddress((void**)&t1,  g_t1);
    cudaGetSymbolAddress((void**)&h2,  g_h2);
    cudaGetSymbolAddress((void**)&q,   g_q);
    cudaGetSymbolAddress((void**)&k,   g_k);
    cudaGetSymbolAddress((void**)&v,   g_v);
    cudaGetSymbolAddress((void**)&s,   g_s);
    cudaGetSymbolAddress((void**)&agg, g_agg);
    cudaGetSymbolAddress((void**)&t2,  g_t2);
    cudaGetSymbolAddress((void**)&t3,  g_t3);
    cudaGetSymbolAddress((void**)&h4,  g_h4);

    const dim3 blk(128);
    const dim3 blk256(256);

    // small config: 64x64 tile, warp 32x32
    const dim3 gSq(DD_ / 64, NN_ / 64);          // (4, 64)
    const dim3 gOut(OUTD_ / 64, NN_ / 64);       // (2, 64)
    // big config: 128x128 tile, warp 64x64
    const dim3 gQkv(QKVD_ / 128, NN_ / 128);         // (8, 32)
    const dim3 gScore(NN_ / 128, NN_ / 128, HH_);    // (32, 32, 4)
    const dim3 gPV(DD_ / 128, NN_ / 128, HH_);       // (2, 32, 4)

    // 1) h1 = elu(x @ w_in + b_in + x)
    gemm_tc<64, 64, 32, 32, false, 1, true><<<gSq, blk>>>(x, DD_, 0, w_in, DD_, 0,
        b_in, x, DD_, h1, DD_, 0, DD_, 1.f);

    // 2) t1 = relu(h1 @ w_m1 + b_m1 + h1);  h2 = LN(t1)
    gemm_tc<64, 64, 32, 32, false, 2, true><<<gSq, blk>>>(h1, DD_, 0, w_m1, DD_, 0,
        b_m1, h1, DD_, t1, DD_, 0, DD_, 1.f);
    ln_k<<<NN_, blk256>>>(t1, g_m1, be_m1, h2);

    // 3) q/k/v projections
    gemm_tc<128, 128, 64, 64, false, 0, false><<<gQkv, blk>>>(h2, DD_, 0, wq, QKVD_, 0,
        bq, nullptr, 0, q, QKVD_, 0, DD_, 1.f);
    gemm_tc<128, 128, 64, 64, false, 0, false><<<gQkv, blk>>>(h2, DD_, 0, wk, QKVD_, 0,
        bk, nullptr, 0, k, QKVD_, 0, DD_, 1.f);
    gemm_tc<128, 128, 64, 64, false, 0, false><<<gQkv, blk>>>(h2, DD_, 0, wv, QKVD_, 0,
        bv, nullptr, 0, v, QKVD_, 0, DD_, 1.f);

    // 4) scores: s[h] = (1/16) * Q_h @ K_h^T
    gemm_tc<128, 128, 64, 64, true, 0, false><<<gScore, blk>>>(q, QKVD_, DHH_,
        k, QKVD_, DHH_, nullptr, nullptr, 0, s, NN_, (long)NN_ * NN_, DHH_, 1.f / 16.f);

    // 5) softmax over source nodes
    softmax_k<<<HH_ * NN_, blk256>>>(s);

    // 6) agg = h2 @ wskip + bskip
    gemm_tc<64, 64, 32, 32, false, 0, false><<<gSq, blk>>>(h2, DD_, 0, wskip, DD_, 0,
        bskip, nullptr, 0, agg, DD_, 0, DD_, 1.f);

    // 7) per-head PV (alpha=0.25), batched over heads; outputs into q's memory
    gemm_tc<128, 128, 64, 64, false, 0, false><<<gPV, blk>>>(
        s, NN_, (long)NN_ * NN_,
        v, QKVD_, DHH_,
        nullptr, nullptr, 0,
        q, DD_, (long)NN_ * DD_, NN_, 0.25f);

    // 8) t2 = LN(agg + sum_h ph)
    ln_agg_k<<<NN_, blk256>>>(agg, q, g_n1, be_n1, t2);

    // 9) t3 = relu(t2 @ w_m2 + b_m2 + t2);  h4 = LN(t3)
    gemm_tc<64, 64, 32, 32, false, 2, true><<<gSq, blk>>>(t2, DD_, 0, w_m2, DD_, 0,
        b_m2, t2, DD_, t3, DD_, 0, DD_, 1.f);
    ln_k<<<NN_, blk256>>>(t3, g_m2, be_m2, h4);

    // 10) out = h4 @ w_mean + b_mean
    gemm_tc<64, 64, 32, 32, false, 0, false><<<gOut, blk>>>(h4, DD_, 0, w_mean, OUTD_, 0,
        b_mean, nullptr, 0, out, OUTD_, 0, DD_, 1.f);
}

// round 7
// speedup vs baseline: 4.5059x; 1.1466x over previous
#include <cuda_runtime.h>
#include <math.h>
#include <stdint.h>

// Problem dims (fixed)
#define NN_ 4096
#define DD_ 256
#define HH_ 4
#define DHH_ 256
#define QKVD_ 1024
#define OUTD_ 128

// ---------------- scratch (device globals) ------------------------------------
__device__ float g_h1[NN_ * DD_];
__device__ float g_t1[NN_ * DD_];
__device__ float g_h2[NN_ * DD_];
__device__ float g_q[NN_ * QKVD_];     // later reused as 4 per-head PV outputs
__device__ float g_k[NN_ * QKVD_];
__device__ float g_v[NN_ * QKVD_];
__device__ float g_s[(size_t)HH_ * NN_ * NN_];
__device__ float g_agg[NN_ * DD_];
__device__ float g_t2[NN_ * DD_];
__device__ float g_t3[NN_ * DD_];
__device__ float g_h4[NN_ * DD_];

__device__ __forceinline__ uint32_t f2tf32(float f) {
    uint32_t u;
    asm("cvt.rna.tf32.f32 %0, %1;" : "=r"(u) : "f"(f));
    return u;
}

__device__ __forceinline__ void mma_tf32(float* d, const uint32_t* a, const uint32_t* b) {
    asm volatile(
        "mma.sync.aligned.m16n8k8.row.col.f32.tf32.tf32.f32 "
        "{%0,%1,%2,%3}, {%4,%5,%6,%7}, {%8,%9}, {%0,%1,%2,%3};\n"
        : "+f"(d[0]), "+f"(d[1]), "+f"(d[2]), "+f"(d[3])
        : "r"(a[0]), "r"(a[1]), "r"(a[2]), "r"(a[3]), "r"(b[0]), "r"(b[1]));
}

__device__ __forceinline__ void cp_async16(void* smem_dst, const void* gmem_src) {
    uint32_t dst = (uint32_t)__cvta_generic_to_shared(smem_dst);
    asm volatile("cp.async.cg.shared.global [%0], [%1], 16;\n"
                 :: "r"(dst), "l"(gmem_src));
}

// ---------------- TF32 tensor-core GEMM, 3-stage cp.async pipeline -------------
// C = act(alpha*A@B(^T) + bias + res), A [M,K] row-major.
// 128 threads = 4 warps (2x2), warp tile WM x WN of m16n8k8 atoms, BK=16.
// smem holds raw fp32 tiles; tf32 rounding applied at fragment-load time.
// Layouts: As [m][k] pad 20, Bs(transB) [n][k] pad 20, Bs(K-major) [k][n] pad BN+8.
template <int BM, int BN, int WM, int WN, bool TRANSB, int ACT, bool HAS_RES>
__global__ void __launch_bounds__(128, 2) gemm_tc(
    const float* __restrict__ A, int lda, long sAb,
    const float* __restrict__ B, int ldb, long sBb,
    const float* __restrict__ bias,
    const float* __restrict__ res, int ldres,
    float* __restrict__ C, int ldc, long sCb,
    int K, float alpha)
{
    constexpr int BK = 16;
    constexpr int STAGES = 3;
    constexpr int AM = WM / 16;
    constexpr int AN = WN / 8;
    constexpr int PA  = BK + 4;                 // 20
    constexpr int PBT = BK + 4;                 // 20
    constexpr int PBN = BN + 8;
    constexpr int AW = BM * PA;                                // A stage words
    constexpr int BW = TRANSB ? (BN * PBT) : (BK * PBN);       // B stage words
    constexpr int NCA = BM * BK / (4 * 128);    // 16B chunks/thread for A
    constexpr int NCB = BN * BK / (4 * 128);    // same count either B layout

    const int batch = blockIdx.z;
    A += (long)batch * sAb;
    B += (long)batch * sBb;
    C += (long)batch * sCb;

    extern __shared__ float sm[];
    float* AsB = sm;                   // [STAGES][AW]
    float* BsB = sm + STAGES * AW;     // [STAGES][BW]

    const int t    = threadIdx.x;
    const int warp = t >> 5;
    const int lane = t & 31;
    const int g    = lane >> 2;
    const int tig  = lane & 3;
    const int wm0  = (warp >> 1) * WM;
    const int wn0  = (warp & 1) * WN;
    const int row0 = blockIdx.y * BM;
    const int col0 = blockIdx.x * BN;

    float d[AM][AN][4];
#pragma unroll
    for (int am = 0; am < AM; am++)
#pragma unroll
        for (int an = 0; an < AN; an++)
#pragma unroll
            for (int i = 0; i < 4; i++) d[am][an][i] = 0.f;

    // ---- async tile issue (tile index -> stage buffer) ----
    auto issue_tile = [&](int tile, int buf) {
        const int k0 = tile * BK;
        float* Ad = AsB + buf * AW;
        float* Bd = BsB + buf * BW;
#pragma unroll
        for (int i = 0; i < NCA; i++) {
            int c   = t + i * 128;
            int r   = c >> 2;              // 0..BM-1
            int col = (c & 3) * 4;         // 0,4,8,12
            cp_async16(Ad + r * PA + col, &A[(long)(row0 + r) * lda + k0 + col]);
        }
        if (TRANSB) {
#pragma unroll
            for (int i = 0; i < NCB; i++) {
                int c   = t + i * 128;
                int r   = c >> 2;          // n: 0..BN-1
                int col = (c & 3) * 4;     // k
                cp_async16(Bd + r * PBT + col, &B[(long)(col0 + r) * ldb + k0 + col]);
            }
        } else {
#pragma unroll
            for (int i = 0; i < NCB; i++) {
                int c   = t + i * 128;
                int r   = c / (BN / 4);            // k: 0..15
                int col = (c % (BN / 4)) * 4;      // n
                cp_async16(Bd + r * PBN + col, &B[(long)(k0 + r) * ldb + col0 + col]);
            }
        }
    };

    const int nit = K / BK;

    // ---- prologue: fill STAGES-1 buffers ----
#pragma unroll
    for (int s = 0; s < STAGES - 1; s++) {
        issue_tile(s, s);
        asm volatile("cp.async.commit_group;\n" ::);
    }
    asm volatile("cp.async.wait_group %0;\n" :: "n"(STAGES - 2));
    __syncthreads();

    for (int it = 0; it < nit; it++) {
        const int buf = it % STAGES;
        const int pf  = it + STAGES - 1;
        if (pf < nit) issue_tile(pf, pf % STAGES);
        asm volatile("cp.async.commit_group;\n" ::);

        const float* Ab = AsB + buf * AW;
        const float* Bb = BsB + buf * BW;

#pragma unroll
        for (int ks = 0; ks < 2; ks++) {
            const int kk = ks * 8;
            uint32_t a[AM][4], b[AN][2];
#pragma unroll
            for (int am = 0; am < AM; am++) {
                const int mr = wm0 + am * 16 + g;
                a[am][0] = f2tf32(Ab[mr * PA + kk + tig]);
                a[am][1] = f2tf32(Ab[(mr + 8) * PA + kk + tig]);
                a[am][2] = f2tf32(Ab[mr * PA + kk + tig + 4]);
                a[am][3] = f2tf32(Ab[(mr + 8) * PA + kk + tig + 4]);
            }
#pragma unroll
            for (int an = 0; an < AN; an++) {
                const int nc = wn0 + an * 8 + g;
                if (TRANSB) {
                    b[an][0] = f2tf32(Bb[nc * PBT + kk + tig]);
                    b[an][1] = f2tf32(Bb[nc * PBT + kk + tig + 4]);
                } else {
                    b[an][0] = f2tf32(Bb[(kk + tig) * PBN + nc]);
                    b[an][1] = f2tf32(Bb[(kk + tig + 4) * PBN + nc]);
                }
            }
#pragma unroll
            for (int am = 0; am < AM; am++)
#pragma unroll
                for (int an = 0; an < AN; an++)
                    mma_tf32(d[am][an], a[am], b[an]);
        }

        asm volatile("cp.async.wait_group %0;\n" :: "n"(STAGES - 2));
        __syncthreads();
    }

    // ---- epilogue ----
#pragma unroll
    for (int am = 0; am < AM; am++) {
#pragma unroll
        for (int an = 0; an < AN; an++) {
            const int c0 = col0 + wn0 + an * 8 + tig * 2;
#pragma unroll
            for (int half = 0; half < 2; half++) {
                const int r = row0 + wm0 + am * 16 + g + half * 8;
#pragma unroll
                for (int j = 0; j < 2; j++) {
                    const int c = c0 + j;
                    float v = alpha * d[am][an][half * 2 + j];
                    if (bias) v += bias[c];
                    if (HAS_RES) v += res[(long)r * ldres + c];
                    if (ACT == 1) v = (v > 0.f) ? v : expm1f(v);   // ELU
                    if (ACT == 2) v = fmaxf(v, 0.f);               // ReLU
                    C[(long)r * ldc + c] = v;
                }
            }
        }
    }
}

// dynamic smem bytes for a given instantiation
template <int BM, int BN, bool TRANSB>
constexpr int smem_bytes() {
    constexpr int BK = 16, STAGES = 3;
    constexpr int AW = BM * (BK + 4);
    constexpr int BW = TRANSB ? (BN * (BK + 4)) : (BK * (BN + 8));
    return STAGES * (AW + BW) * 4;
}

// ---------------- block reduce (256 threads) -----------------------------------
__device__ __forceinline__ float block_reduce_256(float v, bool do_max)
{
    __shared__ float sm[8];
#pragma unroll
    for (int o = 16; o > 0; o >>= 1) {
        float u = __shfl_xor_sync(0xffffffffu, v, o);
        v = do_max ? fmaxf(v, u) : (v + u);
    }
    const int warp = threadIdx.x >> 5;
    if ((threadIdx.x & 31) == 0) sm[warp] = v;
    __syncthreads();
    float r = sm[0];
#pragma unroll
    for (int i = 1; i < 8; i++) r = do_max ? fmaxf(r, sm[i]) : (r + sm[i]);
    __syncthreads();
    return r;
}

// ---------------- softmax over rows of 4096 (in place) -------------------------
__global__ void __launch_bounds__(256) softmax_k(float* __restrict__ S)
{
    const long row = blockIdx.x;
    float* p = S + row * (long)NN_;
    const int t = threadIdx.x;

    float v[16];
    float m = -1e30f;
#pragma unroll
    for (int i = 0; i < 16; i++) { v[i] = p[i * 256 + t]; m = fmaxf(m, v[i]); }
    m = block_reduce_256(m, true);

    float s = 0.f;
#pragma unroll
    for (int i = 0; i < 16; i++) { v[i] = __expf(v[i] - m); s += v[i]; }
    s = block_reduce_256(s, false);

    const float inv = 1.f / s;
#pragma unroll
    for (int i = 0; i < 16; i++) p[i * 256 + t] = v[i] * inv;
}

// ---------------- LayerNorm over rows of 256 -----------------------------------
__global__ void __launch_bounds__(256) ln_k(
    const float* __restrict__ X, const float* __restrict__ g,
    const float* __restrict__ b, float* __restrict__ Y)
{
    const int row = blockIdx.x;
    const int t = threadIdx.x;
    const float x = X[row * DD_ + t];
    const float mean = block_reduce_256(x, false) * (1.f / 256.f);
    const float d = x - mean;
    const float var = block_reduce_256(d * d, false) * (1.f / 256.f);
    Y[row * DD_ + t] = d * rsqrtf(var + 1e-5f) * g[t] + b[t];
}

// ---- LN of (skip + sum of 4 per-head PV outputs), heads pre-scaled by 0.25 ----
__global__ void __launch_bounds__(256) ln_agg_k(
    const float* __restrict__ skip, const float* __restrict__ ph,
    const float* __restrict__ g, const float* __restrict__ b,
    float* __restrict__ Y)
{
    const int row = blockIdx.x;
    const int t = threadIdx.x;
    const long i = (long)row * DD_ + t;
    const long S = (long)NN_ * DD_;
    const float x = skip[i] + ph[i] + ph[i + S] + ph[i + 2 * S] + ph[i + 3 * S];
    const float mean = block_reduce_256(x, false) * (1.f / 256.f);
    const float d = x - mean;
    const float var = block_reduce_256(d * d, false) * (1.f / 256.f);
    Y[row * DD_ + t] = d * rsqrtf(var + 1e-5f) * g[t] + b[t];
}

// ---------------- launch --------------------------------------------------------
extern "C" void kernel_launch(void* const* d_in, const int* in_sizes, int n_in,
                              void* d_out, int out_size)
{
    const float* x      = (const float*)d_in[0];
    const float* w_in   = (const float*)d_in[1];
    const float* b_in   = (const float*)d_in[2];
    const float* w_m1   = (const float*)d_in[3];
    const float* b_m1   = (const float*)d_in[4];
    const float* g_m1   = (const float*)d_in[5];
    const float* be_m1  = (const float*)d_in[6];
    const float* wq     = (const float*)d_in[7];
    const float* bq     = (const float*)d_in[8];
    const float* wk     = (const float*)d_in[9];
    const float* bk     = (const float*)d_in[10];
    const float* wv     = (const float*)d_in[11];
    const float* bv     = (const float*)d_in[12];
    const float* wskip  = (const float*)d_in[13];
    const float* bskip  = (const float*)d_in[14];
    const float* g_n1   = (const float*)d_in[15];
    const float* be_n1  = (const float*)d_in[16];
    const float* w_m2   = (const float*)d_in[17];
    const float* b_m2   = (const float*)d_in[18];
    const float* g_m2   = (const float*)d_in[19];
    const float* be_m2  = (const float*)d_in[20];
    const float* w_mean = (const float*)d_in[21];
    const float* b_mean = (const float*)d_in[22];
    float* out = (float*)d_out;

    float *h1, *t1, *h2, *q, *k, *v, *s, *agg, *t2, *t3, *h4;
    cudaGetSymbolAddress((void**)&h1,  g_h1);
    cudaGetSymbolAddress((void**)&t1,  g_t1);
    cudaGetSymbolAddress((void**)&h2,  g_h2);
    cudaGetSymbolAddress((void**)&q,   g_q);
    cudaGetSymbolAddress((void**)&k,   g_k);
    cudaGetSymbolAddress((void**)&v,   g_v);
    cudaGetSymbolAddress((void**)&s,   g_s);
    cudaGetSymbolAddress((void**)&agg, g_agg);
    cudaGetSymbolAddress((void**)&t2,  g_t2);
    cudaGetSymbolAddress((void**)&t3,  g_t3);
    cudaGetSymbolAddress((void**)&h4,  g_h4);

    // opt-in to >48KB dynamic smem (host-side, capture-time only)
    constexpr int SM_SQ_ELU  = smem_bytes<64, 64, false>();
    constexpr int SM_BIG     = smem_bytes<128, 128, false>();
    constexpr int SM_BIG_T   = smem_bytes<128, 128, true>();
    cudaFuncSetAttribute(gemm_tc<64, 64, 32, 32, false, 1, true>,
        cudaFuncAttributeMaxDynamicSharedMemorySize, SM_SQ_ELU);
    cudaFuncSetAttribute(gemm_tc<64, 64, 32, 32, false, 2, true>,
        cudaFuncAttributeMaxDynamicSharedMemorySize, SM_SQ_ELU);
    cudaFuncSetAttribute(gemm_tc<64, 64, 32, 32, false, 0, false>,
        cudaFuncAttributeMaxDynamicSharedMemorySize, SM_SQ_ELU);
    cudaFuncSetAttribute(gemm_tc<128, 128, 64, 64, false, 0, false>,
        cudaFuncAttributeMaxDynamicSharedMemorySize, SM_BIG);
    cudaFuncSetAttribute(gemm_tc<128, 128, 64, 64, true, 0, false>,
        cudaFuncAttributeMaxDynamicSharedMemorySize, SM_BIG_T);

    const dim3 blk(128);
    const dim3 blk256(256);

    // small config: 64x64 tile, warp 32x32
    const dim3 gSq(DD_ / 64, NN_ / 64);          // (4, 64)
    const dim3 gOut(OUTD_ / 64, NN_ / 64);       // (2, 64)
    // big config: 128x128 tile, warp 64x64
    const dim3 gQkv(QKVD_ / 128, NN_ / 128);         // (8, 32)
    const dim3 gScore(NN_ / 128, NN_ / 128, HH_);    // (32, 32, 4)
    const dim3 gPV(DD_ / 128, NN_ / 128, HH_);       // (2, 32, 4)

    // 1) h1 = elu(x @ w_in + b_in + x)
    gemm_tc<64, 64, 32, 32, false, 1, true><<<gSq, blk, SM_SQ_ELU>>>(x, DD_, 0,
        w_in, DD_, 0, b_in, x, DD_, h1, DD_, 0, DD_, 1.f);

    // 2) t1 = relu(h1 @ w_m1 + b_m1 + h1);  h2 = LN(t1)
    gemm_tc<64, 64, 32, 32, false, 2, true><<<gSq, blk, SM_SQ_ELU>>>(h1, DD_, 0,
        w_m1, DD_, 0, b_m1, h1, DD_, t1, DD_, 0, DD_, 1.f);
    ln_k<<<NN_, blk256>>>(t1, g_m1, be_m1, h2);

    // 3) q/k/v projections
    gemm_tc<128, 128, 64, 64, false, 0, false><<<gQkv, blk, SM_BIG>>>(h2, DD_, 0,
        wq, QKVD_, 0, bq, nullptr, 0, q, QKVD_, 0, DD_, 1.f);
    gemm_tc<128, 128, 64, 64, false, 0, false><<<gQkv, blk, SM_BIG>>>(h2, DD_, 0,
        wk, QKVD_, 0, bk, nullptr, 0, k, QKVD_, 0, DD_, 1.f);
    gemm_tc<128, 128, 64, 64, false, 0, false><<<gQkv, blk, SM_BIG>>>(h2, DD_, 0,
        wv, QKVD_, 0, bv, nullptr, 0, v, QKVD_, 0, DD_, 1.f);

    // 4) scores: s[h] = (1/16) * Q_h @ K_h^T
    gemm_tc<128, 128, 64, 64, true, 0, false><<<gScore, blk, SM_BIG_T>>>(
        q, QKVD_, DHH_, k, QKVD_, DHH_, nullptr, nullptr, 0,
        s, NN_, (long)NN_ * NN_, DHH_, 1.f / 16.f);

    // 5) softmax over source nodes
    softmax_k<<<HH_ * NN_, blk256>>>(s);

    // 6) agg = h2 @ wskip + bskip
    gemm_tc<64, 64, 32, 32, false, 0, false><<<gSq, blk, SM_SQ_ELU>>>(h2, DD_, 0,
        wskip, DD_, 0, bskip, nullptr, 0, agg, DD_, 0, DD_, 1.f);

    // 7) per-head PV (alpha=0.25), batched over heads; outputs into q's memory
    gemm_tc<128, 128, 64, 64, false, 0, false><<<gPV, blk, SM_BIG>>>(
        s, NN_, (long)NN_ * NN_,
        v, QKVD_, DHH_,
        nullptr, nullptr, 0,
        q, DD_, (long)NN_ * DD_, NN_, 0.25f);

    // 8) t2 = LN(agg + sum_h ph)
    ln_agg_k<<<NN_, blk256>>>(agg, q, g_n1, be_n1, t2);

    // 9) t3 = relu(t2 @ w_m2 + b_m2 + t2);  h4 = LN(t3)
    gemm_tc<64, 64, 32, 32, false, 2, true><<<gSq, blk, SM_SQ_ELU>>>(t2, DD_, 0,
        w_m2, DD_, 0, b_m2, t2, DD_, t3, DD_, 0, DD_, 1.f);
    ln_k<<<NN_, blk256>>>(t3, g_m2, be_m2, h4);

    // 10) out = h4 @ w_mean + b_mean
    gemm_tc<64, 64, 32, 32, false, 0, false><<<gOut, blk, SM_SQ_ELU>>>(h4, DD_, 0,
        w_mean, OUTD_, 0, b_mean, nullptr, 0, out, OUTD_, 0, DD_, 1.f);
}